// round 10
// baseline (speedup 1.0000x reference)
#include <cuda_runtime.h>

typedef unsigned long long ull;

#define B_    1024
#define N_    64
#define C_    16
#define M_    16
#define H_    512
#define T_    128
#define DIN_  80
#define ROWS  8
#define NTHR  512

// ---- packed f32x2 helpers (FFMA2 path: 2 MACs / instruction) ----
__device__ __forceinline__ ull fdup(float v){
    ull r; asm("mov.b64 %0, {%1, %1};" : "=l"(r) : "f"(v)); return r;
}
__device__ __forceinline__ void funpack(ull v, float &a, float &b){
    asm("mov.b64 {%0, %1}, %2;" : "=f"(a), "=f"(b) : "l"(v));
}
#define FFMA2(acc, a, b) asm("fma.rn.f32x2 %0, %1, %2, %0;" : "+l"(acc) : "l"(a), "l"(b))

__global__ void __launch_bounds__(NTHR, 1)
nsde_kernel(const float* __restrict__ y0,
            const float* __restrict__ controls,
            const float* __restrict__ noise,
            const float* __restrict__ W1mu, const float* __restrict__ b1mu,
            const float* __restrict__ W2mu, const float* __restrict__ b2mu,
            const float* __restrict__ W1sg, const float* __restrict__ b1sg,
            const float* __restrict__ W2sg, const float* __restrict__ b2sg,
            float* __restrict__ out)
{
    __shared__ float sx  [DIN_][ROWS];    // x transposed: [i][row], 32B rows
    __shared__ float shm [H_][ROWS];      // h_mu transposed
    __shared__ float shs [H_][ROWS];      // h_sg transposed
    __shared__ float sy  [ROWS][N_];      // persistent state y
    __shared__ float sz  [ROWS][M_];      // noise * sqrt(dt) this step
    __shared__ float sdpB[8][N_][ROWS];   // drift partials  [seg][col][row]
    __shared__ float sdpC[8][N_][ROWS];   // diffusion partials [mgrp][n][row]

    const int t  = threadIdx.x;
    const int r0 = blockIdx.x * ROWS;

    // init y, write trajectory slice t=0  (ROWS*N_ = 512 = NTHR)
    {
        int b = t >> 6, n = t & 63;
        float v = y0[(r0+b)*N_ + n];
        sy[b][n] = v;
        out[(size_t)(r0+b)*N_ + n] = v;
    }
    __syncthreads();

    for (int k = 0; k < T_-1; k++){
        // ---- build x (transposed) and pre-scaled noise ----
        for (int i = t; i < DIN_*ROWS; i += NTHR){
            int ii = i >> 3, b = i & 7;
            sx[ii][b] = (ii < N_) ? sy[b][ii] : controls[k*C_ + (ii - N_)];
        }
        if (t < ROWS*M_){
            int b = t >> 4, m = t & 15;
            sz[b][m] = noise[((size_t)k*B_ + r0 + b)*M_ + m] * 0.1f;
        }
        __syncthreads();

        // ---- Phase A: h_mu[j], h_sg[j] for j = t; 8-deep dbl-buffered LDG ----
        {
            const int j = t;
            const float* wm = W1mu + j;
            const float* ws = W1sg + j;
            float wm0[8], ws0[8], wm1[8], ws1[8];
            #pragma unroll
            for (int q=0;q<8;q++){
                wm0[q] = wm[(size_t)q*H_];
                ws0[q] = ws[(size_t)q*H_];
            }
            ull am[4], as2[4];
            #pragma unroll
            for (int p=0;p<4;p++){ am[p]=0ull; as2[p]=0ull; }

            #pragma unroll 1
            for (int b2=0; b2<5; b2++){       // 10 blocks of 8, processed in pairs
                const int base = b2*16;
                #pragma unroll
                for (int q=0;q<8;q++){
                    wm1[q] = wm[(size_t)(base+8+q)*H_];
                    ws1[q] = ws[(size_t)(base+8+q)*H_];
                }
                #pragma unroll
                for (int q=0;q<8;q++){
                    const int i = base + q;
                    ull wmd = fdup(wm0[q]), wsd = fdup(ws0[q]);
                    ulonglong2 x0 = *(const ulonglong2*)&sx[i][0];
                    ulonglong2 x1 = *(const ulonglong2*)&sx[i][4];
                    FFMA2(am [0], x0.x, wmd); FFMA2(am [1], x0.y, wmd);
                    FFMA2(am [2], x1.x, wmd); FFMA2(am [3], x1.y, wmd);
                    FFMA2(as2[0], x0.x, wsd); FFMA2(as2[1], x0.y, wsd);
                    FFMA2(as2[2], x1.x, wsd); FFMA2(as2[3], x1.y, wsd);
                }
                if (b2 < 4){
                    #pragma unroll
                    for (int q=0;q<8;q++){
                        wm0[q] = wm[(size_t)(base+16+q)*H_];
                        ws0[q] = ws[(size_t)(base+16+q)*H_];
                    }
                }
                #pragma unroll
                for (int q=0;q<8;q++){
                    const int i = base + 8 + q;
                    ull wmd = fdup(wm1[q]), wsd = fdup(ws1[q]);
                    ulonglong2 x0 = *(const ulonglong2*)&sx[i][0];
                    ulonglong2 x1 = *(const ulonglong2*)&sx[i][4];
                    FFMA2(am [0], x0.x, wmd); FFMA2(am [1], x0.y, wmd);
                    FFMA2(am [2], x1.x, wmd); FFMA2(am [3], x1.y, wmd);
                    FFMA2(as2[0], x0.x, wsd); FFMA2(as2[1], x0.y, wsd);
                    FFMA2(as2[2], x1.x, wsd); FFMA2(as2[3], x1.y, wsd);
                }
            }

            float bm = b1mu[j], bs = b1sg[j];
            float o[8];
            #pragma unroll
            for (int p=0;p<4;p++) funpack(am[p], o[2*p], o[2*p+1]);
            #pragma unroll
            for (int q=0;q<8;q++) o[q] = fmaxf(o[q] + bm, 0.f);
            *(float4*)&shm[j][0] = make_float4(o[0],o[1],o[2],o[3]);
            *(float4*)&shm[j][4] = make_float4(o[4],o[5],o[6],o[7]);
            #pragma unroll
            for (int p=0;p<4;p++) funpack(as2[p], o[2*p], o[2*p+1]);
            #pragma unroll
            for (int q=0;q<8;q++) o[q] = fmaxf(o[q] + bs, 0.f);
            *(float4*)&shs[j][0] = make_float4(o[0],o[1],o[2],o[3]);
            *(float4*)&shs[j][4] = make_float4(o[4],o[5],o[6],o[7]);
        }
        __syncthreads();

        // ---- Fused Phase B+C: diffusion GEMM (all kk) + drift in seg window ----
        {
            const int j0  = 2*t;            // 2 diffusion columns
            const int col = t & 63;         // drift column
            const int seg = t >> 6;         // drift kk-window: [seg*64, seg*64+64)
            const char*  pw = (const char*)(W2sg + j0);   // row stride 4096B
            const float* w2 = W2mu + col;                 // row stride 64 floats

            float2 wc[8], wcn[8];
            #pragma unroll
            for (int q=0;q<8;q++)
                wc[q] = *(const float2*)(pw + (size_t)q*4096);

            float wb[8], wbn[8];
            if (seg == 0){
                #pragma unroll
                for (int q=0;q<8;q++) wb[q] = w2[(size_t)q*N_];
            }

            ull acc[2][4], accB[4];
            #pragma unroll
            for (int c=0;c<2;c++)
                #pragma unroll
                for(int p=0;p<4;p++) acc[c][p]=0ull;
            #pragma unroll
            for (int p=0;p<4;p++) accB[p]=0ull;

            #pragma unroll 1
            for (int b8=0; b8<64; b8++){    // 64 blocks of 8 kk
                const int kb = b8*8;
                if (b8 < 63){
                    #pragma unroll
                    for (int q=0;q<8;q++)
                        wcn[q] = *(const float2*)(pw + (size_t)(kb+8+q)*4096);
                }
                const bool inw  = (b8 >= seg*8) && (b8 < seg*8+8);
                const bool nxtw = (b8+1 >= seg*8) && (b8+1 < seg*8+8);
                if (nxtw){
                    #pragma unroll
                    for (int q=0;q<8;q++) wbn[q] = w2[(size_t)(kb+8+q)*N_];
                }

                if (inw){
                    #pragma unroll
                    for (int q=0;q<8;q++){
                        const int kk = kb + q;
                        ulonglong2 u0 = *(const ulonglong2*)&shs[kk][0];
                        ulonglong2 u1 = *(const ulonglong2*)&shs[kk][4];
                        ull wd0=fdup(wc[q].x), wd1=fdup(wc[q].y);
                        FFMA2(acc[0][0],u0.x,wd0); FFMA2(acc[0][1],u0.y,wd0);
                        FFMA2(acc[0][2],u1.x,wd0); FFMA2(acc[0][3],u1.y,wd0);
                        FFMA2(acc[1][0],u0.x,wd1); FFMA2(acc[1][1],u0.y,wd1);
                        FFMA2(acc[1][2],u1.x,wd1); FFMA2(acc[1][3],u1.y,wd1);
                        ulonglong2 h0 = *(const ulonglong2*)&shm[kk][0];
                        ulonglong2 h1 = *(const ulonglong2*)&shm[kk][4];
                        ull wdb = fdup(wb[q]);
                        FFMA2(accB[0], h0.x, wdb); FFMA2(accB[1], h0.y, wdb);
                        FFMA2(accB[2], h1.x, wdb); FFMA2(accB[3], h1.y, wdb);
                    }
                } else {
                    #pragma unroll
                    for (int q=0;q<8;q++){
                        const int kk = kb + q;
                        ulonglong2 u0 = *(const ulonglong2*)&shs[kk][0];
                        ulonglong2 u1 = *(const ulonglong2*)&shs[kk][4];
                        ull wd0=fdup(wc[q].x), wd1=fdup(wc[q].y);
                        FFMA2(acc[0][0],u0.x,wd0); FFMA2(acc[0][1],u0.y,wd0);
                        FFMA2(acc[0][2],u1.x,wd0); FFMA2(acc[0][3],u1.y,wd0);
                        FFMA2(acc[1][0],u0.x,wd1); FFMA2(acc[1][1],u0.y,wd1);
                        FFMA2(acc[1][2],u1.x,wd1); FFMA2(acc[1][3],u1.y,wd1);
                    }
                }
                if (nxtw){
                    #pragma unroll
                    for (int q=0;q<8;q++) wb[q] = wbn[q];
                }
                #pragma unroll
                for (int q=0;q<8;q++) wc[q] = wcn[q];
            }

            // B epilogue: drift partials
            #pragma unroll
            for (int p=0;p<4;p++){
                float a, b2v; funpack(accB[p], a, b2v);
                sdpB[seg][col][2*p]   = a;
                sdpB[seg][col][2*p+1] = b2v;
            }

            // C epilogue: columns j0,j0+1 -> (n = t>>3, m = 2g, 2g+1), g = t&7
            const int n  = t >> 3;
            const int g  = t & 7;
            float bias0 = b2sg[j0], bias1 = b2sg[j0+1];
            float cont[ROWS];
            #pragma unroll
            for (int p=0;p<4;p++){
                float a0, b0, a1, b1v;
                funpack(acc[0][p], a0, b0);
                funpack(acc[1][p], a1, b1v);
                cont[2*p]   = (a0  + bias0) * sz[2*p  ][2*g]
                            + (a1  + bias1) * sz[2*p  ][2*g+1];
                cont[2*p+1] = (b0  + bias0) * sz[2*p+1][2*g]
                            + (b1v + bias1) * sz[2*p+1][2*g+1];
            }
            #pragma unroll
            for (int b=0;b<ROWS;b++) sdpC[g][n][b] = cont[b];
        }
        __syncthreads();

        // ---- y update (drift reduce fused) + trajectory write ----
        {
            int n = t & 63, b = t >> 6;
            float dr = b2mu[n];
            #pragma unroll
            for (int g=0; g<8; g++) dr += sdpB[g][n][b];
            float yn = sy[b][n] + 0.01f * dr;
            #pragma unroll
            for (int g=0; g<8; g++) yn += sdpC[g][n][b];
            sy[b][n] = yn;
            out[((size_t)(k+1)*B_ + r0 + b)*N_ + n] = yn;
        }
        __syncthreads();
    }
}

extern "C" void kernel_launch(void* const* d_in, const int* in_sizes, int n_in,
                              void* d_out, int out_size)
{
    (void)in_sizes; (void)n_in; (void)out_size;
    nsde_kernel<<<B_/ROWS, NTHR>>>(
        (const float*)d_in[0],  // y0
        (const float*)d_in[1],  // controls
        (const float*)d_in[2],  // noise
        (const float*)d_in[3],  // W1_mu
        (const float*)d_in[4],  // b1_mu
        (const float*)d_in[5],  // W2_mu
        (const float*)d_in[6],  // b2_mu
        (const float*)d_in[7],  // W1_sg
        (const float*)d_in[8],  // b1_sg
        (const float*)d_in[9],  // W2_sg
        (const float*)d_in[10], // b2_sg
        (float*)d_out);
}

// round 11
// speedup vs baseline: 1.3109x; 1.3109x over previous
#include <cuda_runtime.h>

typedef unsigned long long ull;

#define B_    1024
#define N_    64
#define C_    16
#define M_    16
#define H_    512
#define T_    128
#define DIN_  80
#define ROWS  8
#define NTHR  512

// ---- packed f32x2 helpers (FFMA2 path: 2 MACs / instruction) ----
__device__ __forceinline__ ull fdup(float v){
    ull r; asm("mov.b64 %0, {%1, %1};" : "=l"(r) : "f"(v)); return r;
}
__device__ __forceinline__ void funpack(ull v, float &a, float &b){
    asm("mov.b64 {%0, %1}, %2;" : "=f"(a), "=f"(b) : "l"(v));
}
#define FFMA2(acc, a, b) asm("fma.rn.f32x2 %0, %1, %2, %0;" : "+l"(acc) : "l"(a), "l"(b))

struct SM {
    float sx  [DIN_][ROWS];     // x transposed: [i][row], 32B rows
    float shm [H_][ROWS];       // h_mu transposed
    float shs [H_][ROWS];       // h_sg transposed
    float sy  [ROWS][N_];       // persistent state y
    float sz  [ROWS][M_];       // noise * sqrt(dt) this step
    float sdpB[8][N_][ROWS];    // drift partials  [seg][col][row]
    float sdpC[8][N_][ROWS];    // diffusion contracted partials [mgrp][n][row]
    float part[2][N_*M_][ROWS]; // split-k diffusion partials [half][j][row]
};
#define SMEM_BYTES ((int)sizeof(SM))

__global__ void __launch_bounds__(NTHR, 1)
nsde_kernel(const float* __restrict__ y0,
            const float* __restrict__ controls,
            const float* __restrict__ noise,
            const float* __restrict__ W1mu, const float* __restrict__ b1mu,
            const float* __restrict__ W2mu, const float* __restrict__ b2mu,
            const float* __restrict__ W1sg, const float* __restrict__ b1sg,
            const float* __restrict__ W2sg, const float* __restrict__ b2sg,
            float* __restrict__ out)
{
    extern __shared__ char smem_raw[];
    SM* s = (SM*)smem_raw;

    const int t  = threadIdx.x;
    const int r0 = blockIdx.x * ROWS;

    // init y, write trajectory slice t=0  (ROWS*N_ = 512 = NTHR)
    {
        int b = t >> 6, n = t & 63;
        float v = y0[(r0+b)*N_ + n];
        s->sy[b][n] = v;
        out[(size_t)(r0+b)*N_ + n] = v;
    }
    __syncthreads();

    for (int k = 0; k < T_-1; k++){
        // ---- build x (transposed) and pre-scaled noise ----
        for (int i = t; i < DIN_*ROWS; i += NTHR){
            int ii = i >> 3, b = i & 7;
            s->sx[ii][b] = (ii < N_) ? s->sy[b][ii] : controls[k*C_ + (ii - N_)];
        }
        if (t < ROWS*M_){
            int b = t >> 4, m = t & 15;
            s->sz[b][m] = noise[((size_t)k*B_ + r0 + b)*M_ + m] * 0.1f;
        }
        __syncthreads();

        // ---- Phase A: h_mu[j], h_sg[j] for j = t; 8-deep dbl-buffered LDG ----
        {
            const int j = t;
            const float* wm = W1mu + j;
            const float* ws = W1sg + j;
            float wm0[8], ws0[8], wm1[8], ws1[8];
            #pragma unroll
            for (int q=0;q<8;q++){
                wm0[q] = wm[(size_t)q*H_];
                ws0[q] = ws[(size_t)q*H_];
            }
            ull am[4], as2[4];
            #pragma unroll
            for (int p=0;p<4;p++){ am[p]=0ull; as2[p]=0ull; }

            #pragma unroll 1
            for (int b2=0; b2<5; b2++){       // 10 blocks of 8, processed in pairs
                const int base = b2*16;
                #pragma unroll
                for (int q=0;q<8;q++){
                    wm1[q] = wm[(size_t)(base+8+q)*H_];
                    ws1[q] = ws[(size_t)(base+8+q)*H_];
                }
                #pragma unroll
                for (int q=0;q<8;q++){
                    const int i = base + q;
                    ull wmd = fdup(wm0[q]), wsd = fdup(ws0[q]);
                    ulonglong2 x0 = *(const ulonglong2*)&s->sx[i][0];
                    ulonglong2 x1 = *(const ulonglong2*)&s->sx[i][4];
                    FFMA2(am [0], x0.x, wmd); FFMA2(am [1], x0.y, wmd);
                    FFMA2(am [2], x1.x, wmd); FFMA2(am [3], x1.y, wmd);
                    FFMA2(as2[0], x0.x, wsd); FFMA2(as2[1], x0.y, wsd);
                    FFMA2(as2[2], x1.x, wsd); FFMA2(as2[3], x1.y, wsd);
                }
                if (b2 < 4){
                    #pragma unroll
                    for (int q=0;q<8;q++){
                        wm0[q] = wm[(size_t)(base+16+q)*H_];
                        ws0[q] = ws[(size_t)(base+16+q)*H_];
                    }
                }
                #pragma unroll
                for (int q=0;q<8;q++){
                    const int i = base + 8 + q;
                    ull wmd = fdup(wm1[q]), wsd = fdup(ws1[q]);
                    ulonglong2 x0 = *(const ulonglong2*)&s->sx[i][0];
                    ulonglong2 x1 = *(const ulonglong2*)&s->sx[i][4];
                    FFMA2(am [0], x0.x, wmd); FFMA2(am [1], x0.y, wmd);
                    FFMA2(am [2], x1.x, wmd); FFMA2(am [3], x1.y, wmd);
                    FFMA2(as2[0], x0.x, wsd); FFMA2(as2[1], x0.y, wsd);
                    FFMA2(as2[2], x1.x, wsd); FFMA2(as2[3], x1.y, wsd);
                }
            }

            float bm = b1mu[j], bs = b1sg[j];
            float o[8];
            #pragma unroll
            for (int p=0;p<4;p++) funpack(am[p], o[2*p], o[2*p+1]);
            #pragma unroll
            for (int q=0;q<8;q++) o[q] = fmaxf(o[q] + bm, 0.f);
            *(float4*)&s->shm[j][0] = make_float4(o[0],o[1],o[2],o[3]);
            *(float4*)&s->shm[j][4] = make_float4(o[4],o[5],o[6],o[7]);
            #pragma unroll
            for (int p=0;p<4;p++) funpack(as2[p], o[2*p], o[2*p+1]);
            #pragma unroll
            for (int q=0;q<8;q++) o[q] = fmaxf(o[q] + bs, 0.f);
            *(float4*)&s->shs[j][0] = make_float4(o[0],o[1],o[2],o[3]);
            *(float4*)&s->shs[j][4] = make_float4(o[4],o[5],o[6],o[7]);
        }
        __syncthreads();

        // ---- Phase B: drift partials; 8-deep dbl-buffered LDG ----
        {
            const int col = t & 63;
            const int seg = t >> 6;
            const float* w2 = W2mu + (size_t)(seg*64)*N_ + col;
            float wv0[8], wv1[8];
            #pragma unroll
            for (int q=0;q<8;q++) wv0[q] = w2[(size_t)q*N_];
            ull acc[4] = {0ull,0ull,0ull,0ull};

            #pragma unroll 1
            for (int b2=0; b2<4; b2++){       // 8 blocks of 8, in pairs
                const int base = b2*16;
                #pragma unroll
                for (int q=0;q<8;q++) wv1[q] = w2[(size_t)(base+8+q)*N_];
                #pragma unroll
                for (int q=0;q<8;q++){
                    const int ki = seg*64 + base + q;
                    ull wd = fdup(wv0[q]);
                    ulonglong2 h0 = *(const ulonglong2*)&s->shm[ki][0];
                    ulonglong2 h1 = *(const ulonglong2*)&s->shm[ki][4];
                    FFMA2(acc[0], h0.x, wd); FFMA2(acc[1], h0.y, wd);
                    FFMA2(acc[2], h1.x, wd); FFMA2(acc[3], h1.y, wd);
                }
                if (b2 < 3){
                    #pragma unroll
                    for (int q=0;q<8;q++) wv0[q] = w2[(size_t)(base+16+q)*N_];
                }
                #pragma unroll
                for (int q=0;q<8;q++){
                    const int ki = seg*64 + base + 8 + q;
                    ull wd = fdup(wv1[q]);
                    ulonglong2 h0 = *(const ulonglong2*)&s->shm[ki][0];
                    ulonglong2 h1 = *(const ulonglong2*)&s->shm[ki][4];
                    FFMA2(acc[0], h0.x, wd); FFMA2(acc[1], h0.y, wd);
                    FFMA2(acc[2], h1.x, wd); FFMA2(acc[3], h1.y, wd);
                }
            }
            #pragma unroll
            for (int p=0;p<4;p++){
                float a, b2v; funpack(acc[p], a, b2v);
                s->sdpB[seg][col][2*p]   = a;
                s->sdpB[seg][col][2*p+1] = b2v;
            }
        }
        __syncthreads();

        // ---- Phase C main: split-k diffusion GEMM (4 cols x half the k) ----
        {
            const int tt    = t & 255;      // column group
            const int hh    = t >> 8;       // k half: 0 or 1
            const int j0    = 4*tt;
            const int kbase = hh*256;
            const float4* wp = (const float4*)(W2sg + (size_t)kbase*1024 + j0);
            // row stride = 1024 floats = 256 float4

            float4 w0[4], w1[4];
            #pragma unroll
            for (int q=0;q<4;q++) w0[q] = wp[(size_t)q*256];

            ull acc[4][4];
            #pragma unroll
            for (int c=0;c<4;c++)
                #pragma unroll
                for (int p=0;p<4;p++) acc[c][p]=0ull;

            #pragma unroll 1
            for (int b4=0; b4<32; b4++){    // 64 blocks of 4 kk, in pairs
                const int base = b4*8;
                #pragma unroll
                for (int q=0;q<4;q++) w1[q] = wp[(size_t)(base+4+q)*256];
                #pragma unroll
                for (int q=0;q<4;q++){
                    const int kk = kbase + base + q;
                    ulonglong2 u0 = *(const ulonglong2*)&s->shs[kk][0];
                    ulonglong2 u1 = *(const ulonglong2*)&s->shs[kk][4];
                    ull wd0=fdup(w0[q].x), wd1=fdup(w0[q].y);
                    ull wd2=fdup(w0[q].z), wd3=fdup(w0[q].w);
                    FFMA2(acc[0][0],u0.x,wd0); FFMA2(acc[0][1],u0.y,wd0);
                    FFMA2(acc[0][2],u1.x,wd0); FFMA2(acc[0][3],u1.y,wd0);
                    FFMA2(acc[1][0],u0.x,wd1); FFMA2(acc[1][1],u0.y,wd1);
                    FFMA2(acc[1][2],u1.x,wd1); FFMA2(acc[1][3],u1.y,wd1);
                    FFMA2(acc[2][0],u0.x,wd2); FFMA2(acc[2][1],u0.y,wd2);
                    FFMA2(acc[2][2],u1.x,wd2); FFMA2(acc[2][3],u1.y,wd2);
                    FFMA2(acc[3][0],u0.x,wd3); FFMA2(acc[3][1],u0.y,wd3);
                    FFMA2(acc[3][2],u1.x,wd3); FFMA2(acc[3][3],u1.y,wd3);
                }
                if (b4 < 31){
                    #pragma unroll
                    for (int q=0;q<4;q++) w0[q] = wp[(size_t)(base+8+q)*256];
                }
                #pragma unroll
                for (int q=0;q<4;q++){
                    const int kk = kbase + base + 4 + q;
                    ulonglong2 u0 = *(const ulonglong2*)&s->shs[kk][0];
                    ulonglong2 u1 = *(const ulonglong2*)&s->shs[kk][4];
                    ull wd0=fdup(w1[q].x), wd1=fdup(w1[q].y);
                    ull wd2=fdup(w1[q].z), wd3=fdup(w1[q].w);
                    FFMA2(acc[0][0],u0.x,wd0); FFMA2(acc[0][1],u0.y,wd0);
                    FFMA2(acc[0][2],u1.x,wd0); FFMA2(acc[0][3],u1.y,wd0);
                    FFMA2(acc[1][0],u0.x,wd1); FFMA2(acc[1][1],u0.y,wd1);
                    FFMA2(acc[1][2],u1.x,wd1); FFMA2(acc[1][3],u1.y,wd1);
                    FFMA2(acc[2][0],u0.x,wd2); FFMA2(acc[2][1],u0.y,wd2);
                    FFMA2(acc[2][2],u1.x,wd2); FFMA2(acc[2][3],u1.y,wd2);
                    FFMA2(acc[3][0],u0.x,wd3); FFMA2(acc[3][1],u0.y,wd3);
                    FFMA2(acc[3][2],u1.x,wd3); FFMA2(acc[3][3],u1.y,wd3);
                }
            }

            // write split-k partials: part[hh][j0+c][0..7]
            #pragma unroll
            for (int c=0;c<4;c++){
                float o[8];
                #pragma unroll
                for (int p=0;p<4;p++) funpack(acc[c][p], o[2*p], o[2*p+1]);
                *(float4*)&s->part[hh][j0+c][0] = make_float4(o[0],o[1],o[2],o[3]);
                *(float4*)&s->part[hh][j0+c][4] = make_float4(o[4],o[5],o[6],o[7]);
            }
        }
        __syncthreads();

        // ---- Phase C reduce: combine halves + bias + dW contraction ----
        {
            const int j0 = 2*t;             // 2 columns per thread
            const int n  = t >> 3;
            const int g  = t & 7;
            float cont[ROWS];
            #pragma unroll
            for (int b=0;b<ROWS;b++) cont[b] = 0.f;
            #pragma unroll
            for (int c=0;c<2;c++){
                const int j = j0 + c;
                const int m = j & 15;
                float bias = b2sg[j];
                float4 a0 = *(const float4*)&s->part[0][j][0];
                float4 a1 = *(const float4*)&s->part[0][j][4];
                float4 q0 = *(const float4*)&s->part[1][j][0];
                float4 q1 = *(const float4*)&s->part[1][j][4];
                cont[0] += (a0.x + q0.x + bias) * s->sz[0][m];
                cont[1] += (a0.y + q0.y + bias) * s->sz[1][m];
                cont[2] += (a0.z + q0.z + bias) * s->sz[2][m];
                cont[3] += (a0.w + q0.w + bias) * s->sz[3][m];
                cont[4] += (a1.x + q1.x + bias) * s->sz[4][m];
                cont[5] += (a1.y + q1.y + bias) * s->sz[5][m];
                cont[6] += (a1.z + q1.z + bias) * s->sz[6][m];
                cont[7] += (a1.w + q1.w + bias) * s->sz[7][m];
            }
            #pragma unroll
            for (int b=0;b<ROWS;b++) s->sdpC[g][n][b] = cont[b];
        }
        __syncthreads();

        // ---- y update (drift reduce fused) + trajectory write ----
        {
            int n = t & 63, b = t >> 6;
            float dr = b2mu[n];
            #pragma unroll
            for (int g=0; g<8; g++) dr += s->sdpB[g][n][b];
            float yn = s->sy[b][n] + 0.01f * dr;
            #pragma unroll
            for (int g=0; g<8; g++) yn += s->sdpC[g][n][b];
            s->sy[b][n] = yn;
            out[((size_t)(k+1)*B_ + r0 + b)*N_ + n] = yn;
        }
        __syncthreads();
    }
}

extern "C" void kernel_launch(void* const* d_in, const int* in_sizes, int n_in,
                              void* d_out, int out_size)
{
    (void)in_sizes; (void)n_in; (void)out_size;
    cudaFuncSetAttribute(nsde_kernel,
                         cudaFuncAttributeMaxDynamicSharedMemorySize,
                         SMEM_BYTES);
    nsde_kernel<<<B_/ROWS, NTHR, SMEM_BYTES>>>(
        (const float*)d_in[0],  // y0
        (const float*)d_in[1],  // controls
        (const float*)d_in[2],  // noise
        (const float*)d_in[3],  // W1_mu
        (const float*)d_in[4],  // b1_mu
        (const float*)d_in[5],  // W2_mu
        (const float*)d_in[6],  // b2_mu
        (const float*)d_in[7],  // W1_sg
        (const float*)d_in[8],  // b1_sg
        (const float*)d_in[9],  // W2_sg
        (const float*)d_in[10], // b2_sg
        (float*)d_out);
}

// round 12
// speedup vs baseline: 1.3445x; 1.0256x over previous
#include <cuda_runtime.h>

typedef unsigned long long ull;

#define B_    1024
#define N_    64
#define C_    16
#define M_    16
#define H_    512
#define T_    128
#define DIN_  80
#define ROWS  8
#define NTHR  512

// ---- packed f32x2 helpers (FFMA2 path: 2 MACs / instruction) ----
__device__ __forceinline__ ull fdup(float v){
    ull r; asm("mov.b64 %0, {%1, %1};" : "=l"(r) : "f"(v)); return r;
}
__device__ __forceinline__ void funpack(ull v, float &a, float &b){
    asm("mov.b64 {%0, %1}, %2;" : "=f"(a), "=f"(b) : "l"(v));
}
#define FFMA2(acc, a, b) asm("fma.rn.f32x2 %0, %1, %2, %0;" : "+l"(acc) : "l"(a), "l"(b))

struct SM {
    float sx  [DIN_][ROWS];     // x transposed [i][row]; rows 0..63 ARE the state y
    float shm [H_][ROWS];       // h_mu transposed
    float shs [H_][ROWS];       // h_sg transposed
    float sz  [ROWS][M_];       // noise * sqrt(dt) this step
    float sdpB[8][N_][ROWS];    // drift partials  [seg][col][row]
    float sdpC[8][N_][ROWS];    // diffusion contracted partials [mgrp][n][row]
    float part[2][N_*M_][ROWS]; // split-k diffusion partials [half][j][row]
};
#define SMEM_BYTES ((int)sizeof(SM))

__global__ void __launch_bounds__(NTHR, 1)
nsde_kernel(const float* __restrict__ y0,
            const float* __restrict__ controls,
            const float* __restrict__ noise,
            const float* __restrict__ W1mu, const float* __restrict__ b1mu,
            const float* __restrict__ W2mu, const float* __restrict__ b2mu,
            const float* __restrict__ W1sg, const float* __restrict__ b1sg,
            const float* __restrict__ W2sg, const float* __restrict__ b2sg,
            float* __restrict__ out)
{
    extern __shared__ char smem_raw[];
    SM* s = (SM*)smem_raw;

    const int t  = threadIdx.x;
    const int r0 = blockIdx.x * ROWS;

    // init: x = [y0^T ; controls[0]], write trajectory slice t=0
    {
        int b = t >> 6, n = t & 63;
        float v = y0[(r0+b)*N_ + n];
        s->sx[n][b] = v;
        out[(size_t)(r0+b)*N_ + n] = v;
        if (t < C_*ROWS){
            int c = t & 15, bb = t >> 4;
            s->sx[N_+c][bb] = controls[c];
        }
    }
    __syncthreads();

    for (int k = 0; k < T_-1; k++){
        // ---- Phase A: h_mu[j], h_sg[j] for j = t; 8-deep dbl-buffered LDG ----
        {
            const int j = t;
            const float* wm = W1mu + j;
            const float* ws = W1sg + j;
            float wm0[8], ws0[8], wm1[8], ws1[8];
            #pragma unroll
            for (int q=0;q<8;q++){
                wm0[q] = wm[(size_t)q*H_];
                ws0[q] = ws[(size_t)q*H_];
            }
            ull am[4], as2[4];
            #pragma unroll
            for (int p=0;p<4;p++){ am[p]=0ull; as2[p]=0ull; }

            #pragma unroll 1
            for (int b2=0; b2<5; b2++){       // 10 blocks of 8, processed in pairs
                const int base = b2*16;
                #pragma unroll
                for (int q=0;q<8;q++){
                    wm1[q] = wm[(size_t)(base+8+q)*H_];
                    ws1[q] = ws[(size_t)(base+8+q)*H_];
                }
                #pragma unroll
                for (int q=0;q<8;q++){
                    const int i = base + q;
                    ull wmd = fdup(wm0[q]), wsd = fdup(ws0[q]);
                    ulonglong2 x0 = *(const ulonglong2*)&s->sx[i][0];
                    ulonglong2 x1 = *(const ulonglong2*)&s->sx[i][4];
                    FFMA2(am [0], x0.x, wmd); FFMA2(am [1], x0.y, wmd);
                    FFMA2(am [2], x1.x, wmd); FFMA2(am [3], x1.y, wmd);
                    FFMA2(as2[0], x0.x, wsd); FFMA2(as2[1], x0.y, wsd);
                    FFMA2(as2[2], x1.x, wsd); FFMA2(as2[3], x1.y, wsd);
                }
                if (b2 < 4){
                    #pragma unroll
                    for (int q=0;q<8;q++){
                        wm0[q] = wm[(size_t)(base+16+q)*H_];
                        ws0[q] = ws[(size_t)(base+16+q)*H_];
                    }
                }
                #pragma unroll
                for (int q=0;q<8;q++){
                    const int i = base + 8 + q;
                    ull wmd = fdup(wm1[q]), wsd = fdup(ws1[q]);
                    ulonglong2 x0 = *(const ulonglong2*)&s->sx[i][0];
                    ulonglong2 x1 = *(const ulonglong2*)&s->sx[i][4];
                    FFMA2(am [0], x0.x, wmd); FFMA2(am [1], x0.y, wmd);
                    FFMA2(am [2], x1.x, wmd); FFMA2(am [3], x1.y, wmd);
                    FFMA2(as2[0], x0.x, wsd); FFMA2(as2[1], x0.y, wsd);
                    FFMA2(as2[2], x1.x, wsd); FFMA2(as2[3], x1.y, wsd);
                }
            }

            float bm = b1mu[j], bs = b1sg[j];
            float o[8];
            #pragma unroll
            for (int p=0;p<4;p++) funpack(am[p], o[2*p], o[2*p+1]);
            #pragma unroll
            for (int q=0;q<8;q++) o[q] = fmaxf(o[q] + bm, 0.f);
            *(float4*)&s->shm[j][0] = make_float4(o[0],o[1],o[2],o[3]);
            *(float4*)&s->shm[j][4] = make_float4(o[4],o[5],o[6],o[7]);
            #pragma unroll
            for (int p=0;p<4;p++) funpack(as2[p], o[2*p], o[2*p+1]);
            #pragma unroll
            for (int q=0;q<8;q++) o[q] = fmaxf(o[q] + bs, 0.f);
            *(float4*)&s->shs[j][0] = make_float4(o[0],o[1],o[2],o[3]);
            *(float4*)&s->shs[j][4] = make_float4(o[4],o[5],o[6],o[7]);
        }
        __syncthreads();

        // ==== Fused phase B + C main (no barrier between: disjoint smem) ====
        {
            // --- C prefetch issued FIRST: its L2 latency hides under B ---
            const int tt    = t & 255;      // column group
            const int hh    = t >> 8;       // k half: 0 or 1
            const int j0c   = 4*tt;
            const int kbase = hh*256;
            const float4* wp = (const float4*)(W2sg + (size_t)kbase*1024 + j0c);
            float4 w0[4], w1[4];
            #pragma unroll
            for (int q=0;q<4;q++) w0[q] = wp[(size_t)q*256];

            // --- noise for this step (consumed in C-reduce, after sync) ---
            if (t < ROWS*M_){
                int b = t >> 4, m = t & 15;
                s->sz[b][m] = noise[((size_t)k*B_ + r0 + b)*M_ + m] * 0.1f;
            }

            // --- Phase B: drift partials; 8-deep dbl-buffered LDG ---
            {
                const int col = t & 63;
                const int seg = t >> 6;
                const float* w2 = W2mu + (size_t)(seg*64)*N_ + col;
                float wv0[8], wv1[8];
                #pragma unroll
                for (int q=0;q<8;q++) wv0[q] = w2[(size_t)q*N_];
                ull acc[4] = {0ull,0ull,0ull,0ull};

                #pragma unroll 1
                for (int b2=0; b2<4; b2++){   // 8 blocks of 8, in pairs
                    const int base = b2*16;
                    #pragma unroll
                    for (int q=0;q<8;q++) wv1[q] = w2[(size_t)(base+8+q)*N_];
                    #pragma unroll
                    for (int q=0;q<8;q++){
                        const int ki = seg*64 + base + q;
                        ull wd = fdup(wv0[q]);
                        ulonglong2 h0 = *(const ulonglong2*)&s->shm[ki][0];
                        ulonglong2 h1 = *(const ulonglong2*)&s->shm[ki][4];
                        FFMA2(acc[0], h0.x, wd); FFMA2(acc[1], h0.y, wd);
                        FFMA2(acc[2], h1.x, wd); FFMA2(acc[3], h1.y, wd);
                    }
                    if (b2 < 3){
                        #pragma unroll
                        for (int q=0;q<8;q++) wv0[q] = w2[(size_t)(base+16+q)*N_];
                    }
                    #pragma unroll
                    for (int q=0;q<8;q++){
                        const int ki = seg*64 + base + 8 + q;
                        ull wd = fdup(wv1[q]);
                        ulonglong2 h0 = *(const ulonglong2*)&s->shm[ki][0];
                        ulonglong2 h1 = *(const ulonglong2*)&s->shm[ki][4];
                        FFMA2(acc[0], h0.x, wd); FFMA2(acc[1], h0.y, wd);
                        FFMA2(acc[2], h1.x, wd); FFMA2(acc[3], h1.y, wd);
                    }
                }
                #pragma unroll
                for (int p=0;p<4;p++){
                    float a, b2v; funpack(acc[p], a, b2v);
                    s->sdpB[seg][col][2*p]   = a;
                    s->sdpB[seg][col][2*p+1] = b2v;
                }
            }

            // --- Phase C main: split-k diffusion GEMM (4 cols x half k) ---
            {
                ull acc[4][4];
                #pragma unroll
                for (int c=0;c<4;c++)
                    #pragma unroll
                    for (int p=0;p<4;p++) acc[c][p]=0ull;

                #pragma unroll 1
                for (int b4=0; b4<32; b4++){    // 64 blocks of 4 kk, in pairs
                    const int base = b4*8;
                    #pragma unroll
                    for (int q=0;q<4;q++) w1[q] = wp[(size_t)(base+4+q)*256];
                    #pragma unroll
                    for (int q=0;q<4;q++){
                        const int kk = kbase + base + q;
                        ulonglong2 u0 = *(const ulonglong2*)&s->shs[kk][0];
                        ulonglong2 u1 = *(const ulonglong2*)&s->shs[kk][4];
                        ull wd0=fdup(w0[q].x), wd1=fdup(w0[q].y);
                        ull wd2=fdup(w0[q].z), wd3=fdup(w0[q].w);
                        FFMA2(acc[0][0],u0.x,wd0); FFMA2(acc[0][1],u0.y,wd0);
                        FFMA2(acc[0][2],u1.x,wd0); FFMA2(acc[0][3],u1.y,wd0);
                        FFMA2(acc[1][0],u0.x,wd1); FFMA2(acc[1][1],u0.y,wd1);
                        FFMA2(acc[1][2],u1.x,wd1); FFMA2(acc[1][3],u1.y,wd1);
                        FFMA2(acc[2][0],u0.x,wd2); FFMA2(acc[2][1],u0.y,wd2);
                        FFMA2(acc[2][2],u1.x,wd2); FFMA2(acc[2][3],u1.y,wd2);
                        FFMA2(acc[3][0],u0.x,wd3); FFMA2(acc[3][1],u0.y,wd3);
                        FFMA2(acc[3][2],u1.x,wd3); FFMA2(acc[3][3],u1.y,wd3);
                    }
                    if (b4 < 31){
                        #pragma unroll
                        for (int q=0;q<4;q++) w0[q] = wp[(size_t)(base+8+q)*256];
                    }
                    #pragma unroll
                    for (int q=0;q<4;q++){
                        const int kk = kbase + base + 4 + q;
                        ulonglong2 u0 = *(const ulonglong2*)&s->shs[kk][0];
                        ulonglong2 u1 = *(const ulonglong2*)&s->shs[kk][4];
                        ull wd0=fdup(w1[q].x), wd1=fdup(w1[q].y);
                        ull wd2=fdup(w1[q].z), wd3=fdup(w1[q].w);
                        FFMA2(acc[0][0],u0.x,wd0); FFMA2(acc[0][1],u0.y,wd0);
                        FFMA2(acc[0][2],u1.x,wd0); FFMA2(acc[0][3],u1.y,wd0);
                        FFMA2(acc[1][0],u0.x,wd1); FFMA2(acc[1][1],u0.y,wd1);
                        FFMA2(acc[1][2],u1.x,wd1); FFMA2(acc[1][3],u1.y,wd1);
                        FFMA2(acc[2][0],u0.x,wd2); FFMA2(acc[2][1],u0.y,wd2);
                        FFMA2(acc[2][2],u1.x,wd2); FFMA2(acc[2][3],u1.y,wd2);
                        FFMA2(acc[3][0],u0.x,wd3); FFMA2(acc[3][1],u0.y,wd3);
                        FFMA2(acc[3][2],u1.x,wd3); FFMA2(acc[3][3],u1.y,wd3);
                    }
                }

                // write split-k partials: part[hh][j0c+c][0..7]
                #pragma unroll
                for (int c=0;c<4;c++){
                    float o[8];
                    #pragma unroll
                    for (int p=0;p<4;p++) funpack(acc[c][p], o[2*p], o[2*p+1]);
                    *(float4*)&s->part[hh][j0c+c][0] = make_float4(o[0],o[1],o[2],o[3]);
                    *(float4*)&s->part[hh][j0c+c][4] = make_float4(o[4],o[5],o[6],o[7]);
                }
            }
        }
        __syncthreads();

        // ---- Phase C reduce: combine halves + bias + dW contraction ----
        {
            const int j0 = 2*t;             // 2 columns per thread
            const int n  = t >> 3;
            const int g  = t & 7;
            float cont[ROWS];
            #pragma unroll
            for (int b=0;b<ROWS;b++) cont[b] = 0.f;
            #pragma unroll
            for (int c=0;c<2;c++){
                const int j = j0 + c;
                const int m = j & 15;
                float bias = b2sg[j];
                float4 a0 = *(const float4*)&s->part[0][j][0];
                float4 a1 = *(const float4*)&s->part[0][j][4];
                float4 q0 = *(const float4*)&s->part[1][j][0];
                float4 q1 = *(const float4*)&s->part[1][j][4];
                cont[0] += (a0.x + q0.x + bias) * s->sz[0][m];
                cont[1] += (a0.y + q0.y + bias) * s->sz[1][m];
                cont[2] += (a0.z + q0.z + bias) * s->sz[2][m];
                cont[3] += (a0.w + q0.w + bias) * s->sz[3][m];
                cont[4] += (a1.x + q1.x + bias) * s->sz[4][m];
                cont[5] += (a1.y + q1.y + bias) * s->sz[5][m];
                cont[6] += (a1.z + q1.z + bias) * s->sz[6][m];
                cont[7] += (a1.w + q1.w + bias) * s->sz[7][m];
            }
            #pragma unroll
            for (int b=0;b<ROWS;b++) s->sdpC[g][n][b] = cont[b];
        }
        __syncthreads();

        // ---- y update (drift reduce fused) + next x build + traj write ----
        {
            int n = t & 63, b = t >> 6;
            float dr = b2mu[n];
            #pragma unroll
            for (int g=0; g<8; g++) dr += s->sdpB[g][n][b];
            float yn = s->sx[n][b] + 0.01f * dr;
            #pragma unroll
            for (int g=0; g<8; g++) yn += s->sdpC[g][n][b];
            s->sx[n][b] = yn;
            out[((size_t)(k+1)*B_ + r0 + b)*N_ + n] = yn;
            if (t < C_*ROWS){
                int c = t & 15, bb = t >> 4;
                s->sx[N_+c][bb] = controls[(k+1)*C_ + c];
            }
        }
        __syncthreads();
    }
}

extern "C" void kernel_launch(void* const* d_in, const int* in_sizes, int n_in,
                              void* d_out, int out_size)
{
    (void)in_sizes; (void)n_in; (void)out_size;
    cudaFuncSetAttribute(nsde_kernel,
                         cudaFuncAttributeMaxDynamicSharedMemorySize,
                         SMEM_BYTES);
    nsde_kernel<<<B_/ROWS, NTHR, SMEM_BYTES>>>(
        (const float*)d_in[0],  // y0
        (const float*)d_in[1],  // controls
        (const float*)d_in[2],  // noise
        (const float*)d_in[3],  // W1_mu
        (const float*)d_in[4],  // b1_mu
        (const float*)d_in[5],  // W2_mu
        (const float*)d_in[6],  // b2_mu
        (const float*)d_in[7],  // W1_sg
        (const float*)d_in[8],  // b1_sg
        (const float*)d_in[9],  // W2_sg
        (const float*)d_in[10], // b2_sg
        (float*)d_out);
}

// round 15
// speedup vs baseline: 1.3658x; 1.0158x over previous
#include <cuda_runtime.h>

typedef unsigned long long ull;

#define B_    1024
#define N_    64
#define C_    16
#define M_    16
#define H_    512
#define T_    128
#define DIN_  80
#define ROWS  8
#define NTHR  512

// ---- packed f32x2 helpers (FFMA2 path: 2 MACs / instruction) ----
__device__ __forceinline__ ull fdup(float v){
    ull r; asm("mov.b64 %0, {%1, %1};" : "=l"(r) : "f"(v)); return r;
}
__device__ __forceinline__ void funpack(ull v, float &a, float &b){
    asm("mov.b64 {%0, %1}, %2;" : "=f"(a), "=f"(b) : "l"(v));
}
#define FFMA2(acc, a, b) asm("fma.rn.f32x2 %0, %1, %2, %0;" : "+l"(acc) : "l"(a), "l"(b))

struct SM {
    float sx  [N_][ROWS];       // state y transposed [n][row]
    float sxu [C_];             // controls for current step (shared by rows)
    float shm [H_][ROWS];       // h_mu transposed
    float shs [H_][ROWS];       // h_sg transposed
    float sz  [ROWS][M_];       // noise * sqrt(dt) this step
    float sdpB[8][N_][9];       // drift partials [seg][col][row] (pad 8->9)
    float part[2][N_*M_][ROWS]; // split-k diffusion partials [half][j][row]
};
#define SMEM_BYTES ((int)sizeof(SM))

__global__ void __launch_bounds__(NTHR, 1)
nsde_kernel(const float* __restrict__ y0,
            const float* __restrict__ controls,
            const float* __restrict__ noise,
            const float* __restrict__ W1mu, const float* __restrict__ b1mu,
            const float* __restrict__ W2mu, const float* __restrict__ b2mu,
            const float* __restrict__ W1sg, const float* __restrict__ b1sg,
            const float* __restrict__ W2sg, const float* __restrict__ b2sg,
            float* __restrict__ out)
{
    extern __shared__ char smem_raw[];
    SM* s = (SM*)smem_raw;

    const int t  = threadIdx.x;
    const int r0 = blockIdx.x * ROWS;

    // init: y state transposed + controls[0], write trajectory slice t=0
    {
        int b = t >> 6, n = t & 63;
        float v = y0[(r0+b)*N_ + n];
        s->sx[n][b] = v;
        out[(size_t)(r0+b)*N_ + n] = v;
        if (t < C_) s->sxu[t] = controls[t];
    }
    __syncthreads();

    for (int k = 0; k < T_-1; k++){
        // ---- Phase A: h_mu[j], h_sg[j] for j = t ----
        {
            const int j = t;
            const float* wm = W1mu + j;
            const float* ws = W1sg + j;

            // control term (rows identical across batch): compute once
            float cu_m = 0.f, cu_s = 0.f;
            #pragma unroll
            for (int c=0;c<C_;c++){
                float u = s->sxu[c];                      // broadcast LDS
                cu_m = fmaf(u, wm[(size_t)(N_+c)*H_], cu_m);
                cu_s = fmaf(u, ws[(size_t)(N_+c)*H_], cu_s);
            }

            float wm0[8], ws0[8], wm1[8], ws1[8];
            #pragma unroll
            for (int q=0;q<8;q++){
                wm0[q] = wm[(size_t)q*H_];
                ws0[q] = ws[(size_t)q*H_];
            }
            ull am[4], as2[4];
            ull cm = fdup(cu_m), cs = fdup(cu_s);
            #pragma unroll
            for (int p=0;p<4;p++){ am[p]=cm; as2[p]=cs; }   // ALL row-pairs get control term

            #pragma unroll 1
            for (int b2=0; b2<4; b2++){       // 8 blocks of 8 (y part), in pairs
                const int base = b2*16;
                #pragma unroll
                for (int q=0;q<8;q++){
                    wm1[q] = wm[(size_t)(base+8+q)*H_];
                    ws1[q] = ws[(size_t)(base+8+q)*H_];
                }
                #pragma unroll
                for (int q=0;q<8;q++){
                    const int i = base + q;
                    ull wmd = fdup(wm0[q]), wsd = fdup(ws0[q]);
                    ulonglong2 x0 = *(const ulonglong2*)&s->sx[i][0];
                    ulonglong2 x1 = *(const ulonglong2*)&s->sx[i][4];
                    FFMA2(am [0], x0.x, wmd); FFMA2(am [1], x0.y, wmd);
                    FFMA2(am [2], x1.x, wmd); FFMA2(am [3], x1.y, wmd);
                    FFMA2(as2[0], x0.x, wsd); FFMA2(as2[1], x0.y, wsd);
                    FFMA2(as2[2], x1.x, wsd); FFMA2(as2[3], x1.y, wsd);
                }
                if (b2 < 3){
                    #pragma unroll
                    for (int q=0;q<8;q++){
                        wm0[q] = wm[(size_t)(base+16+q)*H_];
                        ws0[q] = ws[(size_t)(base+16+q)*H_];
                    }
                }
                #pragma unroll
                for (int q=0;q<8;q++){
                    const int i = base + 8 + q;
                    ull wmd = fdup(wm1[q]), wsd = fdup(ws1[q]);
                    ulonglong2 x0 = *(const ulonglong2*)&s->sx[i][0];
                    ulonglong2 x1 = *(const ulonglong2*)&s->sx[i][4];
                    FFMA2(am [0], x0.x, wmd); FFMA2(am [1], x0.y, wmd);
                    FFMA2(am [2], x1.x, wmd); FFMA2(am [3], x1.y, wmd);
                    FFMA2(as2[0], x0.x, wsd); FFMA2(as2[1], x0.y, wsd);
                    FFMA2(as2[2], x1.x, wsd); FFMA2(as2[3], x1.y, wsd);
                }
            }

            float bm = b1mu[j], bs = b1sg[j];
            float o[8];
            #pragma unroll
            for (int p=0;p<4;p++) funpack(am[p], o[2*p], o[2*p+1]);
            #pragma unroll
            for (int q=0;q<8;q++) o[q] = fmaxf(o[q] + bm, 0.f);
            *(float4*)&s->shm[j][0] = make_float4(o[0],o[1],o[2],o[3]);
            *(float4*)&s->shm[j][4] = make_float4(o[4],o[5],o[6],o[7]);
            #pragma unroll
            for (int p=0;p<4;p++) funpack(as2[p], o[2*p], o[2*p+1]);
            #pragma unroll
            for (int q=0;q<8;q++) o[q] = fmaxf(o[q] + bs, 0.f);
            *(float4*)&s->shs[j][0] = make_float4(o[0],o[1],o[2],o[3]);
            *(float4*)&s->shs[j][4] = make_float4(o[4],o[5],o[6],o[7]);
        }
        __syncthreads();

        // ==== Fused phase B + C main (disjoint smem, one barrier after) ====
        {
            // --- B's first weight block FIRST (B consumes first) ---
            const int col = t & 63;
            const int seg = t >> 6;
            const float* w2 = W2mu + (size_t)(seg*64)*N_ + col;
            float wv0[8], wv1[8];
            #pragma unroll
            for (int q=0;q<8;q++) wv0[q] = w2[(size_t)q*N_];

            // --- C prefetch: latency hides under B's compute ---
            const int tt    = t & 255;      // column group
            const int hh    = t >> 8;       // k half: 0 or 1
            const int j0c   = 4*tt;
            const int kbase = hh*256;
            const float4* wp = (const float4*)(W2sg + (size_t)kbase*1024 + j0c);
            float4 w0[4], w1[4];
            #pragma unroll
            for (int q=0;q<4;q++) w0[q] = wp[(size_t)q*256];

            // --- noise (consumed after the barrier) ---
            if (t < ROWS*M_){
                int b = t >> 4, m = t & 15;
                s->sz[b][m] = noise[((size_t)k*B_ + r0 + b)*M_ + m] * 0.1f;
            }

            // --- Phase B: drift partials; 8-deep dbl-buffered LDG ---
            {
                ull acc[4] = {0ull,0ull,0ull,0ull};
                #pragma unroll 1
                for (int b2=0; b2<4; b2++){   // 8 blocks of 8, in pairs
                    const int base = b2*16;
                    #pragma unroll
                    for (int q=0;q<8;q++) wv1[q] = w2[(size_t)(base+8+q)*N_];
                    #pragma unroll
                    for (int q=0;q<8;q++){
                        const int ki = seg*64 + base + q;
                        ull wd = fdup(wv0[q]);
                        ulonglong2 h0 = *(const ulonglong2*)&s->shm[ki][0];
                        ulonglong2 h1 = *(const ulonglong2*)&s->shm[ki][4];
                        FFMA2(acc[0], h0.x, wd); FFMA2(acc[1], h0.y, wd);
                        FFMA2(acc[2], h1.x, wd); FFMA2(acc[3], h1.y, wd);
                    }
                    if (b2 < 3){
                        #pragma unroll
                        for (int q=0;q<8;q++) wv0[q] = w2[(size_t)(base+16+q)*N_];
                    }
                    #pragma unroll
                    for (int q=0;q<8;q++){
                        const int ki = seg*64 + base + 8 + q;
                        ull wd = fdup(wv1[q]);
                        ulonglong2 h0 = *(const ulonglong2*)&s->shm[ki][0];
                        ulonglong2 h1 = *(const ulonglong2*)&s->shm[ki][4];
                        FFMA2(acc[0], h0.x, wd); FFMA2(acc[1], h0.y, wd);
                        FFMA2(acc[2], h1.x, wd); FFMA2(acc[3], h1.y, wd);
                    }
                }
                #pragma unroll
                for (int p=0;p<4;p++){
                    float a, b2v; funpack(acc[p], a, b2v);
                    s->sdpB[seg][col][2*p]   = a;
                    s->sdpB[seg][col][2*p+1] = b2v;
                }
            }

            // --- Phase C main: split-k diffusion GEMM (4 cols x half k) ---
            {
                ull acc[4][4];
                #pragma unroll
                for (int c=0;c<4;c++)
                    #pragma unroll
                    for (int p=0;p<4;p++) acc[c][p]=0ull;

                #pragma unroll 1
                for (int b4=0; b4<32; b4++){    // 64 blocks of 4 kk, in pairs
                    const int base = b4*8;
                    #pragma unroll
                    for (int q=0;q<4;q++) w1[q] = wp[(size_t)(base+4+q)*256];
                    #pragma unroll
                    for (int q=0;q<4;q++){
                        const int kk = kbase + base + q;
                        ulonglong2 u0 = *(const ulonglong2*)&s->shs[kk][0];
                        ulonglong2 u1 = *(const ulonglong2*)&s->shs[kk][4];
                        ull wd0=fdup(w0[q].x), wd1=fdup(w0[q].y);
                        ull wd2=fdup(w0[q].z), wd3=fdup(w0[q].w);
                        FFMA2(acc[0][0],u0.x,wd0); FFMA2(acc[0][1],u0.y,wd0);
                        FFMA2(acc[0][2],u1.x,wd0); FFMA2(acc[0][3],u1.y,wd0);
                        FFMA2(acc[1][0],u0.x,wd1); FFMA2(acc[1][1],u0.y,wd1);
                        FFMA2(acc[1][2],u1.x,wd1); FFMA2(acc[1][3],u1.y,wd1);
                        FFMA2(acc[2][0],u0.x,wd2); FFMA2(acc[2][1],u0.y,wd2);
                        FFMA2(acc[2][2],u1.x,wd2); FFMA2(acc[2][3],u1.y,wd2);
                        FFMA2(acc[3][0],u0.x,wd3); FFMA2(acc[3][1],u0.y,wd3);
                        FFMA2(acc[3][2],u1.x,wd3); FFMA2(acc[3][3],u1.y,wd3);
                    }
                    if (b4 < 31){
                        #pragma unroll
                        for (int q=0;q<4;q++) w0[q] = wp[(size_t)(base+8+q)*256];
                    }
                    #pragma unroll
                    for (int q=0;q<4;q++){
                        const int kk = kbase + base + 4 + q;
                        ulonglong2 u0 = *(const ulonglong2*)&s->shs[kk][0];
                        ulonglong2 u1 = *(const ulonglong2*)&s->shs[kk][4];
                        ull wd0=fdup(w1[q].x), wd1=fdup(w1[q].y);
                        ull wd2=fdup(w1[q].z), wd3=fdup(w1[q].w);
                        FFMA2(acc[0][0],u0.x,wd0); FFMA2(acc[0][1],u0.y,wd0);
                        FFMA2(acc[0][2],u1.x,wd0); FFMA2(acc[0][3],u1.y,wd0);
                        FFMA2(acc[1][0],u0.x,wd1); FFMA2(acc[1][1],u0.y,wd1);
                        FFMA2(acc[1][2],u1.x,wd1); FFMA2(acc[1][3],u1.y,wd1);
                        FFMA2(acc[2][0],u0.x,wd2); FFMA2(acc[2][1],u0.y,wd2);
                        FFMA2(acc[2][2],u1.x,wd2); FFMA2(acc[2][3],u1.y,wd2);
                        FFMA2(acc[3][0],u0.x,wd3); FFMA2(acc[3][1],u0.y,wd3);
                        FFMA2(acc[3][2],u1.x,wd3); FFMA2(acc[3][3],u1.y,wd3);
                    }
                }

                // write split-k partials: part[hh][j0c+c][0..7]
                #pragma unroll
                for (int c=0;c<4;c++){
                    float o[8];
                    #pragma unroll
                    for (int p=0;p<4;p++) funpack(acc[c][p], o[2*p], o[2*p+1]);
                    *(float4*)&s->part[hh][j0c+c][0] = make_float4(o[0],o[1],o[2],o[3]);
                    *(float4*)&s->part[hh][j0c+c][4] = make_float4(o[4],o[5],o[6],o[7]);
                }
            }
        }
        __syncthreads();

        // ---- Fused C-reduce + drift + y-update (shuffle contraction) ----
        {
            const int n  = t >> 3;          // 0..63
            const int g  = t & 7;           // lane group of 8 shares n
            const int j0 = 2*t;             // = n*16 + 2g
            float cont[ROWS];
            #pragma unroll
            for (int b=0;b<ROWS;b++) cont[b] = 0.f;
            #pragma unroll
            for (int c=0;c<2;c++){
                const int j = j0 + c;
                const int m = j & 15;
                float bias = b2sg[j];
                float4 a0 = *(const float4*)&s->part[0][j][0];
                float4 a1 = *(const float4*)&s->part[0][j][4];
                float4 q0 = *(const float4*)&s->part[1][j][0];
                float4 q1 = *(const float4*)&s->part[1][j][4];
                cont[0] += (a0.x + q0.x + bias) * s->sz[0][m];
                cont[1] += (a0.y + q0.y + bias) * s->sz[1][m];
                cont[2] += (a0.z + q0.z + bias) * s->sz[2][m];
                cont[3] += (a0.w + q0.w + bias) * s->sz[3][m];
                cont[4] += (a1.x + q1.x + bias) * s->sz[4][m];
                cont[5] += (a1.y + q1.y + bias) * s->sz[5][m];
                cont[6] += (a1.z + q1.z + bias) * s->sz[6][m];
                cont[7] += (a1.w + q1.w + bias) * s->sz[7][m];
            }
            // butterfly over the 8 lanes sharing n -> full 16-m contraction
            #pragma unroll
            for (int d=1; d<8; d<<=1){
                #pragma unroll
                for (int b=0;b<ROWS;b++)
                    cont[b] += __shfl_xor_sync(0xffffffffu, cont[b], d, 8);
            }
            // lane g finalizes row b = g
            float dr = b2mu[n];
            #pragma unroll
            for (int gg=0; gg<8; gg++) dr += s->sdpB[gg][n][g];
            float yn = s->sx[n][g] + 0.01f * dr + cont[g];
            s->sx[n][g] = yn;
            out[((size_t)(k+1)*B_ + r0 + g)*N_ + n] = yn;
            if (t < C_) s->sxu[t] = controls[(k+1)*C_ + t];
        }
        __syncthreads();
    }
}

extern "C" void kernel_launch(void* const* d_in, const int* in_sizes, int n_in,
                              void* d_out, int out_size)
{
    (void)in_sizes; (void)n_in; (void)out_size;
    cudaFuncSetAttribute(nsde_kernel,
                         cudaFuncAttributeMaxDynamicSharedMemorySize,
                         SMEM_BYTES);
    nsde_kernel<<<B_/ROWS, NTHR, SMEM_BYTES>>>(
        (const float*)d_in[0],  // y0
        (const float*)d_in[1],  // controls
        (const float*)d_in[2],  // noise
        (const float*)d_in[3],  // W1_mu
        (const float*)d_in[4],  // b1_mu
        (const float*)d_in[5],  // W2_mu
        (const float*)d_in[6],  // b2_mu
        (const float*)d_in[7],  // W1_sg
        (const float*)d_in[8],  // b1_sg
        (const float*)d_in[9],  // W2_sg
        (const float*)d_in[10], // b2_sg
        (float*)d_out);
}

// round 16
// speedup vs baseline: 1.4659x; 1.0733x over previous
#include <cuda_runtime.h>

typedef unsigned long long ull;

#define B_    1024
#define N_    64
#define C_    16
#define M_    16
#define H_    512
#define T_    128
#define DIN_  80
#define ROWS  8
#define NTHR  512

// ---- packed f32x2 helpers (FFMA2 path: 2 MACs / instruction) ----
__device__ __forceinline__ ull fdup(float v){
    ull r; asm("mov.b64 %0, {%1, %1};" : "=l"(r) : "f"(v)); return r;
}
__device__ __forceinline__ void funpack(ull v, float &a, float &b){
    asm("mov.b64 {%0, %1}, %2;" : "=f"(a), "=f"(b) : "l"(v));
}
#define FFMA2(acc, a, b) asm("fma.rn.f32x2 %0, %1, %2, %0;" : "+l"(acc) : "l"(a), "l"(b))

struct SM {
    float sx  [N_][ROWS];       // state y transposed [n][row]
    float sxu [C_];             // controls for current step (shared by rows)
    float shm [H_][ROWS];       // h_mu transposed
    float shs [H_][ROWS];       // h_sg transposed
    float sz  [ROWS][M_];       // noise * sqrt(dt) this step
    float sdpB[8][N_][9];       // drift partials [seg][col][row] (pad 8->9)
    float partC[2][N_][10];     // contracted diffusion partials [half][n][row] (pad 8->10)
};
#define SMEM_BYTES ((int)sizeof(SM))

__global__ void __launch_bounds__(NTHR, 1)
nsde_kernel(const float* __restrict__ y0,
            const float* __restrict__ controls,
            const float* __restrict__ noise,
            const float* __restrict__ W1mu, const float* __restrict__ b1mu,
            const float* __restrict__ W2mu, const float* __restrict__ b2mu,
            const float* __restrict__ W1sg, const float* __restrict__ b1sg,
            const float* __restrict__ W2sg, const float* __restrict__ b2sg,
            float* __restrict__ out)
{
    extern __shared__ char smem_raw[];
    SM* s = (SM*)smem_raw;

    const int t  = threadIdx.x;
    const int r0 = blockIdx.x * ROWS;

    // init: y state transposed + controls[0], write trajectory slice t=0
    {
        int b = t >> 6, n = t & 63;
        float v = y0[(r0+b)*N_ + n];
        s->sx[n][b] = v;
        out[(size_t)(r0+b)*N_ + n] = v;
        if (t < C_) s->sxu[t] = controls[t];
    }
    __syncthreads();

    for (int k = 0; k < T_-1; k++){
        // ---- Phase A: h_mu[j], h_sg[j] for j = t (+ noise load) ----
        {
            // noise for this step (read in C epilogue, after the A barrier)
            if (t < ROWS*M_){
                int b = t >> 4, m = t & 15;
                s->sz[b][m] = noise[((size_t)k*B_ + r0 + b)*M_ + m] * 0.1f;
            }

            const int j = t;
            const float* wm = W1mu + j;
            const float* ws = W1sg + j;

            // control term (rows identical across batch): compute once
            float cu_m = 0.f, cu_s = 0.f;
            #pragma unroll
            for (int c=0;c<C_;c++){
                float u = s->sxu[c];                      // broadcast LDS
                cu_m = fmaf(u, wm[(size_t)(N_+c)*H_], cu_m);
                cu_s = fmaf(u, ws[(size_t)(N_+c)*H_], cu_s);
            }

            float wm0[8], ws0[8], wm1[8], ws1[8];
            #pragma unroll
            for (int q=0;q<8;q++){
                wm0[q] = wm[(size_t)q*H_];
                ws0[q] = ws[(size_t)q*H_];
            }
            ull am[4], as2[4];
            ull cm = fdup(cu_m), cs = fdup(cu_s);
            #pragma unroll
            for (int p=0;p<4;p++){ am[p]=cm; as2[p]=cs; }   // ALL row-pairs get control term

            #pragma unroll 1
            for (int b2=0; b2<4; b2++){       // 8 blocks of 8 (y part), in pairs
                const int base = b2*16;
                #pragma unroll
                for (int q=0;q<8;q++){
                    wm1[q] = wm[(size_t)(base+8+q)*H_];
                    ws1[q] = ws[(size_t)(base+8+q)*H_];
                }
                #pragma unroll
                for (int q=0;q<8;q++){
                    const int i = base + q;
                    ull wmd = fdup(wm0[q]), wsd = fdup(ws0[q]);
                    ulonglong2 x0 = *(const ulonglong2*)&s->sx[i][0];
                    ulonglong2 x1 = *(const ulonglong2*)&s->sx[i][4];
                    FFMA2(am [0], x0.x, wmd); FFMA2(am [1], x0.y, wmd);
                    FFMA2(am [2], x1.x, wmd); FFMA2(am [3], x1.y, wmd);
                    FFMA2(as2[0], x0.x, wsd); FFMA2(as2[1], x0.y, wsd);
                    FFMA2(as2[2], x1.x, wsd); FFMA2(as2[3], x1.y, wsd);
                }
                if (b2 < 3){
                    #pragma unroll
                    for (int q=0;q<8;q++){
                        wm0[q] = wm[(size_t)(base+16+q)*H_];
                        ws0[q] = ws[(size_t)(base+16+q)*H_];
                    }
                }
                #pragma unroll
                for (int q=0;q<8;q++){
                    const int i = base + 8 + q;
                    ull wmd = fdup(wm1[q]), wsd = fdup(ws1[q]);
                    ulonglong2 x0 = *(const ulonglong2*)&s->sx[i][0];
                    ulonglong2 x1 = *(const ulonglong2*)&s->sx[i][4];
                    FFMA2(am [0], x0.x, wmd); FFMA2(am [1], x0.y, wmd);
                    FFMA2(am [2], x1.x, wmd); FFMA2(am [3], x1.y, wmd);
                    FFMA2(as2[0], x0.x, wsd); FFMA2(as2[1], x0.y, wsd);
                    FFMA2(as2[2], x1.x, wsd); FFMA2(as2[3], x1.y, wsd);
                }
            }

            float bm = b1mu[j], bs = b1sg[j];
            float o[8];
            #pragma unroll
            for (int p=0;p<4;p++) funpack(am[p], o[2*p], o[2*p+1]);
            #pragma unroll
            for (int q=0;q<8;q++) o[q] = fmaxf(o[q] + bm, 0.f);
            *(float4*)&s->shm[j][0] = make_float4(o[0],o[1],o[2],o[3]);
            *(float4*)&s->shm[j][4] = make_float4(o[4],o[5],o[6],o[7]);
            #pragma unroll
            for (int p=0;p<4;p++) funpack(as2[p], o[2*p], o[2*p+1]);
            #pragma unroll
            for (int q=0;q<8;q++) o[q] = fmaxf(o[q] + bs, 0.f);
            *(float4*)&s->shs[j][0] = make_float4(o[0],o[1],o[2],o[3]);
            *(float4*)&s->shs[j][4] = make_float4(o[4],o[5],o[6],o[7]);
        }
        __syncthreads();

        // ==== Fused phase B + C main (disjoint smem, one barrier after) ====
        {
            // --- B's first weight block FIRST (B consumes first) ---
            const int col = t & 63;
            const int seg = t >> 6;
            const float* w2 = W2mu + (size_t)(seg*64)*N_ + col;
            float wv0[8], wv1[8];
            #pragma unroll
            for (int q=0;q<8;q++) wv0[q] = w2[(size_t)q*N_];

            // --- C prefetch: latency hides under B's compute ---
            const int tt    = t & 255;      // column group
            const int hh    = t >> 8;       // k half: 0 or 1
            const int j0c   = 4*tt;
            const int kbase = hh*256;
            const float4* wp = (const float4*)(W2sg + (size_t)kbase*1024 + j0c);
            float4 w0[4], w1[4];
            #pragma unroll
            for (int q=0;q<4;q++) w0[q] = wp[(size_t)q*256];

            // --- Phase B: drift partials; 8-deep dbl-buffered LDG ---
            {
                ull acc[4] = {0ull,0ull,0ull,0ull};
                #pragma unroll 1
                for (int b2=0; b2<4; b2++){   // 8 blocks of 8, in pairs
                    const int base = b2*16;
                    #pragma unroll
                    for (int q=0;q<8;q++) wv1[q] = w2[(size_t)(base+8+q)*N_];
                    #pragma unroll
                    for (int q=0;q<8;q++){
                        const int ki = seg*64 + base + q;
                        ull wd = fdup(wv0[q]);
                        ulonglong2 h0 = *(const ulonglong2*)&s->shm[ki][0];
                        ulonglong2 h1 = *(const ulonglong2*)&s->shm[ki][4];
                        FFMA2(acc[0], h0.x, wd); FFMA2(acc[1], h0.y, wd);
                        FFMA2(acc[2], h1.x, wd); FFMA2(acc[3], h1.y, wd);
                    }
                    if (b2 < 3){
                        #pragma unroll
                        for (int q=0;q<8;q++) wv0[q] = w2[(size_t)(base+16+q)*N_];
                    }
                    #pragma unroll
                    for (int q=0;q<8;q++){
                        const int ki = seg*64 + base + 8 + q;
                        ull wd = fdup(wv1[q]);
                        ulonglong2 h0 = *(const ulonglong2*)&s->shm[ki][0];
                        ulonglong2 h1 = *(const ulonglong2*)&s->shm[ki][4];
                        FFMA2(acc[0], h0.x, wd); FFMA2(acc[1], h0.y, wd);
                        FFMA2(acc[2], h1.x, wd); FFMA2(acc[3], h1.y, wd);
                    }
                }
                #pragma unroll
                for (int p=0;p<4;p++){
                    float a, b2v; funpack(acc[p], a, b2v);
                    s->sdpB[seg][col][2*p]   = a;
                    s->sdpB[seg][col][2*p+1] = b2v;
                }
            }

            // --- Phase C main: split-k diffusion GEMM (4 cols x half k) ---
            {
                ull acc[4][4];
                #pragma unroll
                for (int c=0;c<4;c++)
                    #pragma unroll
                    for (int p=0;p<4;p++) acc[c][p]=0ull;

                #pragma unroll 1
                for (int b4=0; b4<32; b4++){    // 64 blocks of 4 kk, in pairs
                    const int base = b4*8;
                    #pragma unroll
                    for (int q=0;q<4;q++) w1[q] = wp[(size_t)(base+4+q)*256];
                    #pragma unroll
                    for (int q=0;q<4;q++){
                        const int kk = kbase + base + q;
                        ulonglong2 u0 = *(const ulonglong2*)&s->shs[kk][0];
                        ulonglong2 u1 = *(const ulonglong2*)&s->shs[kk][4];
                        ull wd0=fdup(w0[q].x), wd1=fdup(w0[q].y);
                        ull wd2=fdup(w0[q].z), wd3=fdup(w0[q].w);
                        FFMA2(acc[0][0],u0.x,wd0); FFMA2(acc[0][1],u0.y,wd0);
                        FFMA2(acc[0][2],u1.x,wd0); FFMA2(acc[0][3],u1.y,wd0);
                        FFMA2(acc[1][0],u0.x,wd1); FFMA2(acc[1][1],u0.y,wd1);
                        FFMA2(acc[1][2],u1.x,wd1); FFMA2(acc[1][3],u1.y,wd1);
                        FFMA2(acc[2][0],u0.x,wd2); FFMA2(acc[2][1],u0.y,wd2);
                        FFMA2(acc[2][2],u1.x,wd2); FFMA2(acc[2][3],u1.y,wd2);
                        FFMA2(acc[3][0],u0.x,wd3); FFMA2(acc[3][1],u0.y,wd3);
                        FFMA2(acc[3][2],u1.x,wd3); FFMA2(acc[3][3],u1.y,wd3);
                    }
                    if (b4 < 31){
                        #pragma unroll
                        for (int q=0;q<4;q++) w0[q] = wp[(size_t)(base+8+q)*256];
                    }
                    #pragma unroll
                    for (int q=0;q<4;q++){
                        const int kk = kbase + base + 4 + q;
                        ulonglong2 u0 = *(const ulonglong2*)&s->shs[kk][0];
                        ulonglong2 u1 = *(const ulonglong2*)&s->shs[kk][4];
                        ull wd0=fdup(w1[q].x), wd1=fdup(w1[q].y);
                        ull wd2=fdup(w1[q].z), wd3=fdup(w1[q].w);
                        FFMA2(acc[0][0],u0.x,wd0); FFMA2(acc[0][1],u0.y,wd0);
                        FFMA2(acc[0][2],u1.x,wd0); FFMA2(acc[0][3],u1.y,wd0);
                        FFMA2(acc[1][0],u0.x,wd1); FFMA2(acc[1][1],u0.y,wd1);
                        FFMA2(acc[1][2],u1.x,wd1); FFMA2(acc[1][3],u1.y,wd1);
                        FFMA2(acc[2][0],u0.x,wd2); FFMA2(acc[2][1],u0.y,wd2);
                        FFMA2(acc[2][2],u1.x,wd2); FFMA2(acc[2][3],u1.y,wd2);
                        FFMA2(acc[3][0],u0.x,wd3); FFMA2(acc[3][1],u0.y,wd3);
                        FFMA2(acc[3][2],u1.x,wd3); FFMA2(acc[3][3],u1.y,wd3);
                    }
                }

                // --- C epilogue: bias + contract with sz NOW, butterfly, store 8 floats ---
                const int nn    = j0c >> 4;       // 0..63
                const int mbase = 4*(t & 3);      // = j0c & 15
                float4 bias4 = *(const float4*)(b2sg + j0c);
                float oc[4][8];
                #pragma unroll
                for (int c=0;c<4;c++)
                    #pragma unroll
                    for (int p=0;p<4;p++) funpack(acc[c][p], oc[c][2*p], oc[c][2*p+1]);
                float cont[8];
                #pragma unroll
                for (int b=0;b<8;b++){
                    float4 zz = *(const float4*)&s->sz[b][mbase];
                    cont[b] = (oc[0][b]+bias4.x)*zz.x + (oc[1][b]+bias4.y)*zz.y
                            + (oc[2][b]+bias4.z)*zz.z + (oc[3][b]+bias4.w)*zz.w;
                }
                // butterfly over the 4 lanes sharing nn -> full 16-m contraction
                #pragma unroll
                for (int d=1; d<4; d<<=1){
                    #pragma unroll
                    for (int b=0;b<8;b++)
                        cont[b] += __shfl_xor_sync(0xffffffffu, cont[b], d, 4);
                }
                if ((t & 3) == 0){
                    float2* dst = (float2*)&s->partC[hh][nn][0];
                    dst[0] = make_float2(cont[0], cont[1]);
                    dst[1] = make_float2(cont[2], cont[3]);
                    dst[2] = make_float2(cont[4], cont[5]);
                    dst[3] = make_float2(cont[6], cont[7]);
                }
            }
        }
        __syncthreads();

        // ---- Final: drift reduce + diffusion combine + y-update + write ----
        {
            int b = t >> 6, n = t & 63;
            float dr = b2mu[n];
            #pragma unroll
            for (int gg=0; gg<8; gg++) dr += s->sdpB[gg][n][b];
            float cont = s->partC[0][n][b] + s->partC[1][n][b];
            float yn = s->sx[n][b] + 0.01f * dr + cont;
            s->sx[n][b] = yn;
            out[((size_t)(k+1)*B_ + r0 + b)*N_ + n] = yn;
            if (t < C_) s->sxu[t] = controls[(k+1)*C_ + t];
        }
        __syncthreads();
    }
}

extern "C" void kernel_launch(void* const* d_in, const int* in_sizes, int n_in,
                              void* d_out, int out_size)
{
    (void)in_sizes; (void)n_in; (void)out_size;
    cudaFuncSetAttribute(nsde_kernel,
                         cudaFuncAttributeMaxDynamicSharedMemorySize,
                         SMEM_BYTES);
    nsde_kernel<<<B_/ROWS, NTHR, SMEM_BYTES>>>(
        (const float*)d_in[0],  // y0
        (const float*)d_in[1],  // controls
        (const float*)d_in[2],  // noise
        (const float*)d_in[3],  // W1_mu
        (const float*)d_in[4],  // b1_mu
        (const float*)d_in[5],  // W2_mu
        (const float*)d_in[6],  // b2_mu
        (const float*)d_in[7],  // W1_sg
        (const float*)d_in[8],  // b1_sg
        (const float*)d_in[9],  // W2_sg
        (const float*)d_in[10], // b2_sg
        (float*)d_out);
}